// round 8
// baseline (speedup 1.0000x reference)
#include <cuda_runtime.h>
#include <cstdint>
#include <cfloat>

// Sparsemax (d = 4096), per-warp max-seeded Michelot with ballot compaction.
//
//   thr_w = warp_max - 1   (<= M-1 <= tau*  => per-warp candidate superset)
//   Each warp compacts its survivors into its own smem segment (ballot
//   prefix, no atomics) and posts partial (sum,count).      [barrier 1]
//   Warp 0 runs Michelot iterations over the ~100 candidates. [barrier 2]
//   out = max(x - tau, 0).
//
// Two barriers per row (was three). Row lives in registers; x read once
// (__ldcs) and out written once (__stcs) — pure streaming traffic.

#define ROW_D     4096
#define THREADS   256
#define NW        (THREADS / 32)
#define V4_PER_T  4
#define SEG       (ROW_D / NW)   // 512 elements per warp segment (worst case)

__global__ __launch_bounds__(THREADS, 6)
void sparsemax_kernel(const float* __restrict__ x, float* __restrict__ out)
{
    __shared__ float2 s_sc[NW];
    __shared__ int    s_wn[NW];
    __shared__ float  s_tau;
    __shared__ float  s_buf[ROW_D];

    const int tid = threadIdx.x;
    const int wid = tid >> 5;
    const int lid = tid & 31;

    const size_t row_base = (size_t)blockIdx.x * ROW_D;
    const float4* __restrict__ xr  = reinterpret_cast<const float4*>(x + row_base);
    float4*       __restrict__ orr = reinterpret_cast<float4*>(out + row_base);

    // ---- load row into registers (streaming, coalesced float4) ----
    float4 v[V4_PER_T];
#pragma unroll
    for (int i = 0; i < V4_PER_T; ++i)
        v[i] = __ldcs(&xr[tid + i * THREADS]);

    // ---- per-warp max -> seed threshold (no block barrier needed) ----
    float m = -FLT_MAX;
#pragma unroll
    for (int i = 0; i < V4_PER_T; ++i) {
        const float4 q = v[i];
        m = fmaxf(m, fmaxf(fmaxf(q.x, q.y), fmaxf(q.z, q.w)));
    }
#pragma unroll
    for (int o = 16; o > 0; o >>= 1)
        m = fmaxf(m, __shfl_xor_sync(0xFFFFFFFFu, m, o));
    const float thr = m - 1.0f;      // <= M-1 <= tau*  => superset of support

    // ---- ballot compaction into this warp's segment + partial (sum,count) ----
    float s = 0.0f, c = 0.0f;
    int   nw = 0;
    const int seg = wid * SEG;
    const unsigned lane_lt = (1u << lid) - 1u;

#pragma unroll
    for (int i = 0; i < V4_PER_T; ++i) {
        const float4 q = v[i];
        {
            const bool p = q.x > thr;
            const unsigned mk = __ballot_sync(0xFFFFFFFFu, p);
            if (p) { s += q.x; c += 1.0f; s_buf[seg + nw + __popc(mk & lane_lt)] = q.x; }
            nw += __popc(mk);
        }
        {
            const bool p = q.y > thr;
            const unsigned mk = __ballot_sync(0xFFFFFFFFu, p);
            if (p) { s += q.y; c += 1.0f; s_buf[seg + nw + __popc(mk & lane_lt)] = q.y; }
            nw += __popc(mk);
        }
        {
            const bool p = q.z > thr;
            const unsigned mk = __ballot_sync(0xFFFFFFFFu, p);
            if (p) { s += q.z; c += 1.0f; s_buf[seg + nw + __popc(mk & lane_lt)] = q.z; }
            nw += __popc(mk);
        }
        {
            const bool p = q.w > thr;
            const unsigned mk = __ballot_sync(0xFFFFFFFFu, p);
            if (p) { s += q.w; c += 1.0f; s_buf[seg + nw + __popc(mk & lane_lt)] = q.w; }
            nw += __popc(mk);
        }
    }
#pragma unroll
    for (int o = 16; o > 0; o >>= 1) {
        s += __shfl_xor_sync(0xFFFFFFFFu, s, o);
        c += __shfl_xor_sync(0xFFFFFFFFu, c, o);
    }
    if (lid == 0) { s_sc[wid] = make_float2(s, c); s_wn[wid] = nw; }
    __syncthreads();                                   // barrier 1

    // ---- warp 0: Michelot over the compacted candidates ----
    if (wid == 0) {
        float S = 0.0f, C = 0.0f;
        int   cn[NW];
#pragma unroll
        for (int w = 0; w < NW; ++w) {
            S += s_sc[w].x;  C += s_sc[w].y;  cn[w] = s_wn[w];
        }
        float tau  = (S - 1.0f) / C;   // iteration 1: full candidate set
        int   prev = (int)C;

        for (int iter = 0; iter < 32; ++iter) {
            float ls = 0.0f, lc = 0.0f;
#pragma unroll
            for (int w = 0; w < NW; ++w) {
                for (int j = lid; j < cn[w]; j += 32) {
                    const float vv = s_buf[w * SEG + j];
                    if (vv > tau) { ls += vv; lc += 1.0f; }
                }
            }
#pragma unroll
            for (int o = 16; o > 0; o >>= 1) {
                ls += __shfl_xor_sync(0xFFFFFFFFu, ls, o);
                lc += __shfl_xor_sync(0xFFFFFFFFu, lc, o);
            }
            const int cnt = (int)lc;   // >= 1: row max always above tau
            tau = (ls - 1.0f) / lc;
            if (cnt == prev) break;    // active set unchanged -> tau exact
            prev = cnt;
        }
        if (lid == 0) s_tau = tau;
    }
    __syncthreads();                                   // barrier 2
    const float tau = s_tau;

    // ---- epilogue: out = max(x - tau, 0), streaming stores ----
#pragma unroll
    for (int i = 0; i < V4_PER_T; ++i) {
        const float4 q = v[i];
        float4 o;
        o.x = fmaxf(q.x - tau, 0.0f);
        o.y = fmaxf(q.y - tau, 0.0f);
        o.z = fmaxf(q.z - tau, 0.0f);
        o.w = fmaxf(q.w - tau, 0.0f);
        __stcs(&orr[tid + i * THREADS], o);
    }
}

extern "C" void kernel_launch(void* const* d_in, const int* in_sizes, int n_in,
                              void* d_out, int out_size)
{
    const float* x   = (const float*)d_in[0];
    float*       out = (float*)d_out;
    const int n_rows = in_sizes[0] / ROW_D;   // 16384
    sparsemax_kernel<<<n_rows, THREADS>>>(x, out);
}

// round 9
// speedup vs baseline: 2.4476x; 2.4476x over previous
#include <cuda_runtime.h>
#include <cstdint>
#include <cfloat>

// Sparsemax (d = 4096), max-seeded Michelot with candidate compaction.
// (R4 structure — best known — plus streaming load/store hints.)
//
//   M = max(row); thr0 = M - 1  (tau* >= M-1, support subset of {x > thr0})
//   Pass 1 doubles as compaction (survivors -> smem) + Michelot iter 1.
//   Remaining iterations: warp 0 only, over the ~60-element compacted set.
//   out = max(x - tau, 0).
//
// Row resident in registers (256 thr x 4 float4); x read once (__ldcs),
// out written once (__stcs) — no L2 write-allocate pollution.

#define ROW_D     4096
#define THREADS   256
#define NW        (THREADS / 32)
#define V4_PER_T  4

__global__ __launch_bounds__(THREADS, 6)
void sparsemax_kernel(const float* __restrict__ x, float* __restrict__ out)
{
    __shared__ float  s_max[NW];
    __shared__ float2 s_sc[NW];
    __shared__ int    s_n;
    __shared__ float  s_tau;
    __shared__ float  s_buf[ROW_D];   // worst case: all elements survive

    const size_t row_base = (size_t)blockIdx.x * ROW_D;
    const float4* __restrict__ xr  = reinterpret_cast<const float4*>(x + row_base);
    float4*       __restrict__ orr = reinterpret_cast<float4*>(out + row_base);

    const int tid = threadIdx.x;
    const int wid = tid >> 5;
    const int lid = tid & 31;

    // ---- load row into registers (streaming, coalesced float4) ----
    float4 v4[V4_PER_T];
#pragma unroll
    for (int i = 0; i < V4_PER_T; ++i)
        v4[i] = __ldcs(&xr[tid + i * THREADS]);

    // ---- pass 1a: row max ----
    float m = -FLT_MAX;
#pragma unroll
    for (int i = 0; i < V4_PER_T; ++i) {
        const float4 q = v4[i];
        m = fmaxf(m, fmaxf(fmaxf(q.x, q.y), fmaxf(q.z, q.w)));
    }
#pragma unroll
    for (int o = 16; o > 0; o >>= 1)
        m = fmaxf(m, __shfl_xor_sync(0xFFFFFFFFu, m, o));
    if (lid == 0) s_max[wid] = m;
    if (tid == 0) s_n = 0;
    __syncthreads();                                   // barrier 1

    float M = s_max[0];
#pragma unroll
    for (int w = 1; w < NW; ++w) M = fmaxf(M, s_max[w]);
    const float thr0 = M - 1.0f;

    // ---- pass 1b: compact survivors + accumulate (sum, count) ----
    float s = 0.0f, c = 0.0f;
    int   myc = 0;
#pragma unroll
    for (int i = 0; i < V4_PER_T; ++i) {
        const float4 q = v4[i];
        if (q.x > thr0) { s += q.x; c += 1.0f; ++myc; }
        if (q.y > thr0) { s += q.y; c += 1.0f; ++myc; }
        if (q.z > thr0) { s += q.z; c += 1.0f; ++myc; }
        if (q.w > thr0) { s += q.w; c += 1.0f; ++myc; }
    }
    if (myc > 0) {
        int pos = atomicAdd(&s_n, myc);
#pragma unroll
        for (int i = 0; i < V4_PER_T; ++i) {
            const float4 q = v4[i];
            if (q.x > thr0) s_buf[pos++] = q.x;
            if (q.y > thr0) s_buf[pos++] = q.y;
            if (q.z > thr0) s_buf[pos++] = q.z;
            if (q.w > thr0) s_buf[pos++] = q.w;
        }
    }
#pragma unroll
    for (int o = 16; o > 0; o >>= 1) {
        s += __shfl_xor_sync(0xFFFFFFFFu, s, o);
        c += __shfl_xor_sync(0xFFFFFFFFu, c, o);
    }
    if (lid == 0) s_sc[wid] = make_float2(s, c);
    __syncthreads();                                   // barrier 2

    // ---- warp 0: Michelot iterations over the compacted set ----
    if (wid == 0) {
        float S = 0.0f, C = 0.0f;
#pragma unroll
        for (int w = 0; w < NW; ++w) { S += s_sc[w].x; C += s_sc[w].y; }
        const int n = s_n;

        float tau  = (S - 1.0f) / C;   // iteration 1 (set = all survivors)
        int   prev = (int)C;

        for (int iter = 0; iter < 32; ++iter) {
            float ls = 0.0f, lc = 0.0f;
            for (int j = lid; j < n; j += 32) {
                const float vv = s_buf[j];
                if (vv > tau) { ls += vv; lc += 1.0f; }
            }
#pragma unroll
            for (int o = 16; o > 0; o >>= 1) {
                ls += __shfl_xor_sync(0xFFFFFFFFu, ls, o);
                lc += __shfl_xor_sync(0xFFFFFFFFu, lc, o);
            }
            const int cnt = (int)lc;        // >= 1: M always > tau
            tau = (ls - 1.0f) / lc;
            if (cnt == prev) break;         // set unchanged -> tau exact
            prev = cnt;
        }
        if (lid == 0) s_tau = tau;
    }
    __syncthreads();                                   // barrier 3
    const float tau = s_tau;

    // ---- epilogue: out = max(x - tau, 0), streaming stores ----
#pragma unroll
    for (int i = 0; i < V4_PER_T; ++i) {
        const float4 q = v4[i];
        float4 o;
        o.x = fmaxf(q.x - tau, 0.0f);
        o.y = fmaxf(q.y - tau, 0.0f);
        o.z = fmaxf(q.z - tau, 0.0f);
        o.w = fmaxf(q.w - tau, 0.0f);
        __stcs(&orr[tid + i * THREADS], o);
    }
}

extern "C" void kernel_launch(void* const* d_in, const int* in_sizes, int n_in,
                              void* d_out, int out_size)
{
    const float* x   = (const float*)d_in[0];
    float*       out = (float*)d_out;
    const int n_rows = in_sizes[0] / ROW_D;   // 16384
    sparsemax_kernel<<<n_rows, THREADS>>>(x, out);
}